// round 6
// baseline (speedup 1.0000x reference)
#include <cuda_runtime.h>
#include <cstdint>

// Cost volume: out[b,d,h,w] = (1/C) * sum_c left[b,c,h,w] * right[b,c,h,w-d], 0 for w<d
// B=8, C=64, H=160, W=320, D=48.

#define BB 8
#define CC 64
#define HH 160
#define WW 320
#define DD 48

#define CK     8              // C-chunk per stage
#define NSTAGE (CC / CK)      // 8
#define PAD    48             // left zero-pad of right row
#define NT     160            // 4 d-groups (x12d) * 40 w-groups (x8w)

// Bank-conflict-free arithmetic swizzle: +4-float gap every 32 floats.
#define SW(i) ((i) + 4 * ((i) >> 5))
#define SLS  356
#define SRS  412
// smem: 2*8*(356+412)*4 = 49152 B = 48 KB exactly -> 3 CTAs/SM.

typedef unsigned long long ull;

__device__ __forceinline__ ull pk(float lo, float hi) {
    ull v; asm("mov.b64 %0, {%1, %2};" : "=l"(v) : "f"(lo), "f"(hi)); return v;
}
__device__ __forceinline__ void ffma2(ull& d, ull a, ull b) {
    asm("fma.rn.f32x2 %0, %1, %2, %0;" : "+l"(d) : "l"(a), "l"(b));
}
__device__ __forceinline__ void fmul2(ull& d, ull a) {
    asm("mul.rn.f32x2 %0, %0, %1;" : "+l"(d) : "l"(a));
}
__device__ __forceinline__ void cpasync16(void* dst_smem, const void* src) {
    uint32_t d = (uint32_t)__cvta_generic_to_shared(dst_smem);
    asm volatile("cp.async.cg.shared.global [%0], [%1], 16;" :: "r"(d), "l"(src) : "memory");
}

__global__ __launch_bounds__(NT, 3) void corvol_kernel(
    const float* __restrict__ left,
    const float* __restrict__ right,
    float* __restrict__ out)
{
    __shared__ __align__(16) float sL[2][CK][SLS];
    __shared__ __align__(16) float sR[2][CK][SRS];

    const int bh  = blockIdx.x;
    const int b   = bh / HH;
    const int h   = bh % HH;
    const int tid = threadIdx.x;

    const int dg = tid / 40;       // 0..3
    const int wg = tid % 40;       // 0..39
    const int d0 = dg * 12;
    const int w0 = wg * 8;

    const float* lb = left  + ((size_t)b * CC * HH + h) * WW;
    const float* rb = right + ((size_t)b * CC * HH + h) * WW;

    // Zero the right-pad region ONCE for both buffers (2*8*12 = 192 float4s).
    for (int i = tid; i < 2 * CK * (PAD / 4); i += NT) {
        const int buf = i / (CK * (PAD / 4));
        const int cc  = (i % (CK * (PAD / 4))) / (PAD / 4);
        const int v   = (i % (PAD / 4)) * 4;
        *(float4*)&sR[buf][cc][SW(v)] = make_float4(0.f, 0.f, 0.f, 0.f);
    }

    ull acc2[12][4];
    #pragma unroll
    for (int di = 0; di < 12; di++)
        #pragma unroll
        for (int j = 0; j < 4; j++)
            acc2[di][j] = 0ull;

    // r[k] = logical sR index q+k, q = PAD + w0 - d0 - 12 (multiple of 4, >= 0).
    // right[w-d] for w=w0+x, d=d0+di lives at r[x - di + 12], x in [0,7], di in [0,11].
    const int q   = PAD + w0 - d0 - 12;
    const int lw0 = SW(w0);
    int rq[5];
    #pragma unroll
    for (int t = 0; t < 5; t++) rq[t] = SW(q + 4 * t);

    // ---- stage 0 copy ----
    #pragma unroll
    for (int i = tid; i < CK * (WW / 4); i += NT) {
        const int cc = i / (WW / 4);
        const int v  = (i % (WW / 4)) * 4;
        const size_t goff = (size_t)cc * (HH * WW) + v;
        cpasync16(&sL[0][cc][SW(v)],       lb + goff);
        cpasync16(&sR[0][cc][SW(PAD + v)], rb + goff);
    }
    asm volatile("cp.async.commit_group;" ::: "memory");

    for (int s = 0; s < NSTAGE; s++) {
        const int cur = s & 1;
        if (s + 1 < NSTAGE) {
            const int nxt = (s + 1) & 1;
            const int c0n = (s + 1) * CK;
            #pragma unroll
            for (int i = tid; i < CK * (WW / 4); i += NT) {
                const int cc = i / (WW / 4);
                const int v  = (i % (WW / 4)) * 4;
                const size_t goff = (size_t)(c0n + cc) * (HH * WW) + v;
                cpasync16(&sL[nxt][cc][SW(v)],       lb + goff);
                cpasync16(&sR[nxt][cc][SW(PAD + v)], rb + goff);
            }
            asm volatile("cp.async.commit_group;" ::: "memory");
            asm volatile("cp.async.wait_group 1;"  ::: "memory");
        } else {
            asm volatile("cp.async.wait_group 0;"  ::: "memory");
        }
        __syncthreads();

        #pragma unroll
        for (int cc = 0; cc < CK; cc++) {
            // Load left/right; alias float quads as 64-bit even-aligned pairs.
            union { float f[8];  ull u[4];  } L;
            union { float f[20]; ull u[10]; } R;

            *(float4*)&L.f[0] = *(const float4*)&sL[cur][cc][lw0];
            *(float4*)&L.f[4] = *(const float4*)&sL[cur][cc][lw0 + 4];
            #pragma unroll
            for (int t = 0; t < 5; t++)
                *(float4*)&R.f[4 * t] = *(const float4*)&sR[cur][cc][rq[t]];

            // Even-offset pairs come free: R.u[k] = (r[2k], r[2k+1]).
            // Even di: pair start r[2j - di + 12] = R.u[j + 6 - di/2].
            #pragma unroll
            for (int di = 0; di < 12; di += 2) {
                #pragma unroll
                for (int j = 0; j < 4; j++)
                    ffma2(acc2[di][j], L.u[j], R.u[j + 6 - di / 2]);
            }

            // Odd-offset pairs need explicit packs: o[m] = (r[2m+1], r[2m+2]).
            ull o[9];
            #pragma unroll
            for (int m = 0; m <= 8; m++) o[m] = pk(R.f[2 * m + 1], R.f[2 * m + 2]);

            // Odd di: pair start r[2j - di + 12] = o[j + (11 - di)/2].
            #pragma unroll
            for (int di = 1; di < 12; di += 2) {
                #pragma unroll
                for (int j = 0; j < 4; j++)
                    ffma2(acc2[di][j], L.u[j], o[j + (11 - di) / 2]);
            }
        }
        __syncthreads();
    }

    const float inv = 1.0f / (float)CC;
    const ull inv2 = pk(inv, inv);
    #pragma unroll
    for (int di = 0; di < 12; di++) {
        #pragma unroll
        for (int j = 0; j < 4; j++) fmul2(acc2[di][j], inv2);
        float* op = out + (((size_t)b * DD + (d0 + di)) * HH + h) * WW + w0;
        *(float4*)op       = *(float4*)&acc2[di][0];
        *(float4*)(op + 4) = *(float4*)&acc2[di][2];
    }
}

extern "C" void kernel_launch(void* const* d_in, const int* in_sizes, int n_in,
                              void* d_out, int out_size)
{
    const float* left  = (const float*)d_in[0];
    const float* right = (const float*)d_in[1];
    float* out = (float*)d_out;
    corvol_kernel<<<BB * HH, NT>>>(left, right, out);
}

// round 7
// speedup vs baseline: 1.3493x; 1.3493x over previous
#include <cuda_runtime.h>
#include <cstdint>

// Cost volume: out[b,d,h,w] = (1/C) * sum_c left[b,c,h,w] * right[b,c,h,w-d], 0 for w<d
// B=8, C=64, H=160, W=320, D=48.

#define BB 8
#define CC 64
#define HH 160
#define WW 320
#define DD 48

#define CK     4               // C-chunk per stage
#define NSTAGE (CC / CK)       // 16
#define PADA   48              // pad of right copy A (for dg even, d0 % 4 == 0)
#define PADB   50              // pad of right copy B (for dg odd,  d0 % 4 == 2)
#define NT     320             // 8 d-groups (x6d) * 40 w-groups (x8w)

// Bank-conflict-free arithmetic swizzle: +4-float gap every 32 floats.
#define SW(i) ((i) + 4 * ((i) >> 5))
#define SLS  356               // left row physical floats
#define SRS  416               // right row physical floats (covers SW(369)+1, mult of 4)
// smem: sL 2*4*356*4 = 11392 B; sR 2*2*4*416*4 = 26624 B; total 38016 B < 48 KB.

typedef unsigned long long ull;

__device__ __forceinline__ ull pk(float lo, float hi) {
    ull v; asm("mov.b64 %0, {%1, %2};" : "=l"(v) : "f"(lo), "f"(hi)); return v;
}
__device__ __forceinline__ void upk(ull v, float& lo, float& hi) {
    asm("mov.b64 {%0, %1}, %2;" : "=f"(lo), "=f"(hi) : "l"(v));
}
// odd pair: (hi of a, lo of b)
__device__ __forceinline__ ull mkodd(ull a, ull b) {
    float a0, a1, b0, b1;
    upk(a, a0, a1);
    upk(b, b0, b1);
    return pk(a1, b0);
}
__device__ __forceinline__ void ffma2(ull& d, ull a, ull b) {
    asm("fma.rn.f32x2 %0, %1, %2, %0;" : "+l"(d) : "l"(a), "l"(b));
}
__device__ __forceinline__ void fmul2(ull& d, ull a) {
    asm("mul.rn.f32x2 %0, %0, %1;" : "+l"(d) : "l"(a));
}
__device__ __forceinline__ void cpasync16(void* dst_smem, const void* src) {
    uint32_t d = (uint32_t)__cvta_generic_to_shared(dst_smem);
    asm volatile("cp.async.cg.shared.global [%0], [%1], 16;" :: "r"(d), "l"(src) : "memory");
}
__device__ __forceinline__ void cpasync8(void* dst_smem, const void* src) {
    uint32_t d = (uint32_t)__cvta_generic_to_shared(dst_smem);
    asm volatile("cp.async.ca.shared.global [%0], [%1], 8;" :: "r"(d), "l"(src) : "memory");
}

__global__ __launch_bounds__(NT, 2) void corvol_kernel(
    const float* __restrict__ left,
    const float* __restrict__ right,
    float* __restrict__ out)
{
    __shared__ __align__(16) float sL[2][CK][SLS];
    __shared__ __align__(16) float sR[2][2][CK][SRS];   // [buf][copy ab][cc]

    const int bh  = blockIdx.x;
    const int b   = bh / HH;
    const int h   = bh % HH;
    const int tid = threadIdx.x;

    const int dg = tid / 40;        // 0..7
    const int wg = tid % 40;        // 0..39
    const int d0 = dg * 6;
    const int w0 = wg * 8;
    const int ab = dg & 1;          // which right copy this thread reads

    const float* lb = left  + ((size_t)b * CC * HH + h) * WW;
    const float* rb = right + ((size_t)b * CC * HH + h) * WW;

    // Zero pad regions of both right copies, both buffers (one pass, never rewritten).
    {
        const float4 z4 = make_float4(0.f, 0.f, 0.f, 0.f);
        // [0,48) for both copies: 2 bufs * 4 cc * 12 float4 = 96 items <= NT
        if (tid < 2 * CK * 12) {
            const int buf = tid / (CK * 12);
            const int cc  = (tid / 12) % CK;
            const int v   = (tid % 12) * 4;
            *(float4*)&sR[buf][0][cc][SW(v)] = z4;
            *(float4*)&sR[buf][1][cc][SW(v)] = z4;
        }
        // copy B also needs floats [48,50): SW(48)=52 contiguous pair
        if (tid < 2 * CK) {
            const int buf = tid / CK;
            const int cc  = tid % CK;
            *(float2*)&sR[buf][1][cc][SW(48)] = make_float2(0.f, 0.f);
        }
    }

    ull acc2[6][4];
    #pragma unroll
    for (int di = 0; di < 6; di++)
        #pragma unroll
        for (int j = 0; j < 4; j++)
            acc2[di][j] = 0ull;

    // Window: floats rf[k] (k=0..15) = right width value (w0 - d0 - 8 + k).
    // Pair for (di, j) starts at k = 8 + 2j - di  (in [3,14]).
    // vbase within the chosen copy: pad + w0 - d0 - 8, multiple of 4 by construction.
    const int vbase = (ab ? PADB : PADA) + w0 - d0 - 8;
    const int lsw  = SW(w0);            // w0 % 32 in {0,8,16,24}: +4 stays in-block
    const int rsw0 = SW(vbase);
    const int rsw1 = SW(vbase + 4);
    const int rsw2 = SW(vbase + 8);
    const int rsw3 = SW(vbase + 12);

    // Staging assignment: exactly one float4 column per thread (NT == CK*80).
    const int scc = tid / 80;           // 0..3
    const int sv  = (tid % 80) * 4;     // 0..316
    const int dL  = SW(sv);
    const int dRa = SW(PADA + sv);
    const int dRb0 = SW(PADB + sv);     // floats {50+sv, 51+sv}: contiguous, 8B aligned
    const int dRb1 = SW(PADB + sv + 2); // floats {52+sv, 53+sv}: contiguous, 8B aligned

    // ---- stage 0 copy ----
    {
        const size_t goff = (size_t)scc * (HH * WW) + sv;
        cpasync16(&sL[0][scc][dL],      lb + goff);
        cpasync16(&sR[0][0][scc][dRa],  rb + goff);
        cpasync8 (&sR[0][1][scc][dRb0], rb + goff);
        cpasync8 (&sR[0][1][scc][dRb1], rb + goff + 2);
    }
    asm volatile("cp.async.commit_group;" ::: "memory");

    for (int s = 0; s < NSTAGE; s++) {
        const int cur = s & 1;
        if (s + 1 < NSTAGE) {
            const int nxt = (s + 1) & 1;
            const size_t goff = (size_t)((s + 1) * CK + scc) * (HH * WW) + sv;
            cpasync16(&sL[nxt][scc][dL],      lb + goff);
            cpasync16(&sR[nxt][0][scc][dRa],  rb + goff);
            cpasync8 (&sR[nxt][1][scc][dRb0], rb + goff);
            cpasync8 (&sR[nxt][1][scc][dRb1], rb + goff + 2);
            asm volatile("cp.async.commit_group;" ::: "memory");
            asm volatile("cp.async.wait_group 1;"  ::: "memory");
        } else {
            asm volatile("cp.async.wait_group 0;"  ::: "memory");
        }
        __syncthreads();

        #pragma unroll
        for (int cc = 0; cc < CK; cc++) {
            const float* lrow = &sL[cur][cc][0];
            const float* rrow = &sR[cur][ab][cc][0];

            // Left pairs: free via 64-bit loads.
            ull Lu[4];
            {
                ulonglong2 t0 = *(const ulonglong2*)(lrow + lsw);
                ulonglong2 t1 = *(const ulonglong2*)(lrow + lsw + 4);
                Lu[0] = t0.x; Lu[1] = t0.y; Lu[2] = t1.x; Lu[3] = t1.y;
            }
            // Right even pairs u[0..7]: free via 64-bit loads.
            ull u[8];
            {
                ulonglong2 t;
                t = *(const ulonglong2*)(rrow + rsw0); u[0] = t.x; u[1] = t.y;
                t = *(const ulonglong2*)(rrow + rsw1); u[2] = t.x; u[3] = t.y;
                t = *(const ulonglong2*)(rrow + rsw2); u[4] = t.x; u[5] = t.y;
                t = *(const ulonglong2*)(rrow + rsw3); u[6] = t.x; u[7] = t.y;
            }
            // Odd pairs o[m] = (rf[2m+1], rf[2m+2]), m = 1..6.
            ull o[7];
            #pragma unroll
            for (int m = 1; m <= 6; m++) o[m] = mkodd(u[m], u[m + 1]);

            // (di, j): pair start k = 8 + 2j - di; even di -> u[k/2], odd -> o[(k-1)/2].
            #pragma unroll
            for (int j = 0; j < 4; j++) {
                ffma2(acc2[0][j], Lu[j], u[4 + j]);
                ffma2(acc2[1][j], Lu[j], o[3 + j]);
                ffma2(acc2[2][j], Lu[j], u[3 + j]);
                ffma2(acc2[3][j], Lu[j], o[2 + j]);
                ffma2(acc2[4][j], Lu[j], u[2 + j]);
                ffma2(acc2[5][j], Lu[j], o[1 + j]);
            }
        }
        __syncthreads();
    }

    const float inv  = 1.0f / (float)CC;
    const ull   inv2 = pk(inv, inv);
    #pragma unroll
    for (int di = 0; di < 6; di++) {
        #pragma unroll
        for (int j = 0; j < 4; j++) fmul2(acc2[di][j], inv2);
        float* op = out + (((size_t)b * DD + (d0 + di)) * HH + h) * WW + w0;
        *(float4*)op       = *(float4*)&acc2[di][0];
        *(float4*)(op + 4) = *(float4*)&acc2[di][2];
    }
}

extern "C" void kernel_launch(void* const* d_in, const int* in_sizes, int n_in,
                              void* d_out, int out_size)
{
    const float* left  = (const float*)d_in[0];
    const float* right = (const float*)d_in[1];
    float* out = (float*)d_out;
    corvol_kernel<<<BB * HH, NT>>>(left, right, out);
}